// round 17
// baseline (speedup 1.0000x reference)
#include <cuda_runtime.h>
#include <cuda_fp16.h>
#include <cstdint>
#include <cstddef>

// EdgeEncoder FUSED single persistent kernel:
//   Phase A: all CTAs project node tiles of batch 0 (tiles < T0).
//   Phase B: first `nproj` CTAs project remaining tiles; others start edge work.
//   Edge tiles claimed via global ticket; proj CTAs join edge when finished.
//   Cross-CTA sync: per-bucket done counters (threadfence+atomic / volatile spin).
// Math identical to R16: fp16 mma m16n8k16, P/Q fp16, rel_err 4.6026e-4 expected.

#define LDH 136
#define MAXROWS 401408
__device__ half P_buf[(size_t)MAXROWS * 128];
__device__ half Q_buf[(size_t)MAXROWS * 128];
__device__ int g_done[4];
__device__ unsigned int g_ticket;

__device__ __forceinline__ uint32_t pack2(float a, float b) {
    half2 h = __floats2half2_rn(a, b);
    return *reinterpret_cast<uint32_t*>(&h);
}
__device__ __forceinline__ float2 unpack2(uint32_t u) {
    return __half22float2(*reinterpret_cast<half2*>(&u));
}
__device__ __forceinline__ uint32_t smem_u32(const void* p) {
    uint32_t a;
    asm("{ .reg .u64 t; cvta.to.shared.u64 t, %1; cvt.u32.u64 %0, t; }" : "=r"(a) : "l"(p));
    return a;
}
__device__ __forceinline__ void cp16(uint32_t dst, const void* src) {
    asm volatile("cp.async.cg.shared.global [%0], [%1], 16;" :: "r"(dst), "l"(src));
}
#define CP_COMMIT() asm volatile("cp.async.commit_group;" ::: "memory")
#define CP_WAIT1()  asm volatile("cp.async.wait_group 1;" ::: "memory")
#define CP_WAIT0()  asm volatile("cp.async.wait_group 0;" ::: "memory")

__device__ __forceinline__ void mma16(float c[4], const uint32_t a[4], uint32_t b0, uint32_t b1) {
    asm("mma.sync.aligned.m16n8k16.row.col.f32.f16.f16.f32 "
        "{%0,%1,%2,%3}, {%4,%5,%6,%7}, {%8,%9}, {%0,%1,%2,%3};"
        : "+f"(c[0]), "+f"(c[1]), "+f"(c[2]), "+f"(c[3])
        : "r"(a[0]), "r"(a[1]), "r"(a[2]), "r"(a[3]), "r"(b0), "r"(b1));
}
__device__ __forceinline__ uint32_t lds32(const half* p) {
    return *reinterpret_cast<const uint32_t*>(p);
}

__device__ __forceinline__ void load_wT(half* __restrict__ WsT,
                                        const float* __restrict__ src, int tid) {
    const int n = tid & 127, kh = tid >> 7;
#pragma unroll
    for (int g = 0; g < 8; ++g) {
        const int kb = kh * 64 + g * 8;
        uint4 u;
        u.x = pack2(src[(kb + 0) * 128 + n], src[(kb + 1) * 128 + n]);
        u.y = pack2(src[(kb + 2) * 128 + n], src[(kb + 3) * 128 + n]);
        u.z = pack2(src[(kb + 4) * 128 + n], src[(kb + 5) * 128 + n]);
        u.w = pack2(src[(kb + 6) * 128 + n], src[(kb + 7) * 128 + n]);
        *reinterpret_cast<uint4*>(WsT + n * LDH + kb) = u;
    }
}

__device__ __forceinline__ void wait_ready(int b, int S0, int S1, int S2, int S3) {
    volatile int* d = g_done;
    for (;;) {
        bool ok = (d[0] == S0);
        if (b >= 1) ok = ok && (d[1] == S1);
        if (b >= 2) ok = ok && (d[2] == S2);
        if (b >= 3) ok = ok && (d[3] == S3);
        if (ok) break;
        __nanosleep(256);
    }
    __threadfence();
}

// ---- proj over tile range [tfirst, tend) with stride; pipelined X prefetch ----
__device__ __forceinline__ void proj_ranged(
    const float* __restrict__ node_emb,
    const float* __restrict__ b1,
    half* WsTa, half* WsTb, half* Xs,
    int tfirst, int tend, int stride,
    int T0, int T1, int T2,
    int tid, int wid, int gq, int tq)
{
    if (tfirst >= tend) return;
    const int m_warp = (wid & 1) * 32;
    const int n_warp = (wid >> 1) * 32;
    const int xr = tid >> 2, xq = tid & 3;

    float b1v[4][2];
#pragma unroll
    for (int nt = 0; nt < 4; ++nt) {
        const int n0 = n_warp + nt * 8 + tq * 2;
        b1v[nt][0] = b1[n0];
        b1v[nt][1] = b1[n0 + 1];
    }

    float4 xv[8];
    {
        const float* src = node_emb + (size_t)(tfirst * 64 + xr) * 128 + xq * 4;
#pragma unroll
        for (int i = 0; i < 8; ++i)
            xv[i] = *reinterpret_cast<const float4*>(src + i * 16);
    }

    for (int t = tfirst; t < tend; t += stride) {
        {
            half* xrow = Xs + xr * LDH + xq * 4;
#pragma unroll
            for (int i = 0; i < 8; ++i) {
                const float4 v = xv[i];
                *reinterpret_cast<uint2*>(xrow + i * 16) =
                    make_uint2(pack2(v.x, v.y), pack2(v.z, v.w));
            }
        }
        {
            int t1 = t + stride; if (t1 >= tend) t1 = t;
            const float* src = node_emb + (size_t)(t1 * 64 + xr) * 128 + xq * 4;
#pragma unroll
            for (int i = 0; i < 8; ++i)
                xv[i] = *reinterpret_cast<const float4*>(src + i * 16);
        }
        __syncthreads();

        const size_t gb = (size_t)t * 64;
        float acc[2][4][4];
#pragma unroll
        for (int mt = 0; mt < 2; ++mt)
#pragma unroll
            for (int nt = 0; nt < 4; ++nt)
#pragma unroll
                for (int k = 0; k < 4; ++k) acc[mt][nt][k] = 0.f;

#pragma unroll
        for (int ks = 0; ks < 8; ++ks) {
            const int k0 = ks * 16;
            uint32_t a[2][4];
#pragma unroll
            for (int mt = 0; mt < 2; ++mt) {
                const int r0 = m_warp + mt * 16 + gq;
                a[mt][0] = lds32(Xs + r0 * LDH + k0 + 2 * tq);
                a[mt][1] = lds32(Xs + (r0 + 8) * LDH + k0 + 2 * tq);
                a[mt][2] = lds32(Xs + r0 * LDH + k0 + 8 + 2 * tq);
                a[mt][3] = lds32(Xs + (r0 + 8) * LDH + k0 + 8 + 2 * tq);
            }
#pragma unroll
            for (int nt = 0; nt < 4; ++nt) {
                const int n0 = n_warp + nt * 8 + gq;
                const uint32_t b0 = lds32(WsTa + n0 * LDH + k0 + 2 * tq);
                const uint32_t b1r = lds32(WsTa + n0 * LDH + k0 + 8 + 2 * tq);
                mma16(acc[0][nt], a[0], b0, b1r);
                mma16(acc[1][nt], a[1], b0, b1r);
            }
        }
#pragma unroll
        for (int nt = 0; nt < 4; ++nt) {
            const int n0 = n_warp + nt * 8 + tq * 2;
#pragma unroll
            for (int mt = 0; mt < 2; ++mt) {
                const int r0 = m_warp + mt * 16 + gq;
                *reinterpret_cast<uint32_t*>(P_buf + (gb + r0) * 128 + n0) =
                    pack2(acc[mt][nt][0] + b1v[nt][0], acc[mt][nt][1] + b1v[nt][1]);
                *reinterpret_cast<uint32_t*>(P_buf + (gb + r0 + 8) * 128 + n0) =
                    pack2(acc[mt][nt][2] + b1v[nt][0], acc[mt][nt][3] + b1v[nt][1]);
                acc[mt][nt][0] = acc[mt][nt][1] = acc[mt][nt][2] = acc[mt][nt][3] = 0.f;
            }
        }

#pragma unroll
        for (int ks = 0; ks < 8; ++ks) {
            const int k0 = ks * 16;
            uint32_t a[2][4];
#pragma unroll
            for (int mt = 0; mt < 2; ++mt) {
                const int r0 = m_warp + mt * 16 + gq;
                a[mt][0] = lds32(Xs + r0 * LDH + k0 + 2 * tq);
                a[mt][1] = lds32(Xs + (r0 + 8) * LDH + k0 + 2 * tq);
                a[mt][2] = lds32(Xs + r0 * LDH + k0 + 8 + 2 * tq);
                a[mt][3] = lds32(Xs + (r0 + 8) * LDH + k0 + 8 + 2 * tq);
            }
#pragma unroll
            for (int nt = 0; nt < 4; ++nt) {
                const int n0 = n_warp + nt * 8 + gq;
                const uint32_t b0 = lds32(WsTb + n0 * LDH + k0 + 2 * tq);
                const uint32_t b1r = lds32(WsTb + n0 * LDH + k0 + 8 + 2 * tq);
                mma16(acc[0][nt], a[0], b0, b1r);
                mma16(acc[1][nt], a[1], b0, b1r);
            }
        }
#pragma unroll
        for (int nt = 0; nt < 4; ++nt) {
            const int n0 = n_warp + nt * 8 + tq * 2;
#pragma unroll
            for (int mt = 0; mt < 2; ++mt) {
                const int r0 = m_warp + mt * 16 + gq;
                *reinterpret_cast<uint32_t*>(Q_buf + (gb + r0) * 128 + n0) =
                    pack2(acc[mt][nt][0], acc[mt][nt][1]);
                *reinterpret_cast<uint32_t*>(Q_buf + (gb + r0 + 8) * 128 + n0) =
                    pack2(acc[mt][nt][2], acc[mt][nt][3]);
            }
        }
        __threadfence();
        __syncthreads();   // Xs WAR + store visibility before count
        if (tid == 0) {
            const int b = (t < T0) ? 0 : (t < T1) ? 1 : (t < T2) ? 2 : 3;
            atomicAdd(&g_done[b], 1);
        }
    }
}

// smem byte offsets (union of proj and edge layouts)
#define P_WA 0
#define P_WB 34816
#define P_XS 69632
#define E_QB   0
#define E_PB   32768
#define E_HB   65536
#define E_SEL  82944
#define E_IDX  83456
#define E_W1C  84480
#define SMB    87040

__global__ void init_sync_kernel() {
    if (threadIdx.x < 4) g_done[threadIdx.x] = 0;
    if (threadIdx.x == 0) g_ticket = 0u;
}

__global__ void __launch_bounds__(256, 2) fused_kernel(
    const float* __restrict__ node_emb,
    const int* __restrict__ edge_index,
    const float* __restrict__ edge_sel,
    const float* __restrict__ W1,
    const float* __restrict__ b1,
    const float* __restrict__ W2,
    const float* __restrict__ b2,
    float* __restrict__ out,
    int E, int bpb, int n_nodes, int ntiles_e, int ntiles_p, int nproj)
{
    extern __shared__ char smc[];
    __shared__ unsigned s_tk[2];

    const int tid  = threadIdx.x;
    const int wid  = tid >> 5;
    const int lane = tid & 31;
    const int gq   = lane >> 2;
    const int tq   = lane & 3;

    const int T0 = (1 * n_nodes + 63) / 64;
    const int T1 = (2 * n_nodes + 63) / 64;
    const int T2 = (3 * n_nodes + 63) / 64;
    const int S0 = T0, S1 = T1 - T0, S2 = T2 - T1, S3 = ntiles_p - T2;

    // ================= PROJ phases =================
    {
        half* WsTa = reinterpret_cast<half*>(smc + P_WA);
        half* WsTb = reinterpret_cast<half*>(smc + P_WB);
        half* Xs   = reinterpret_cast<half*>(smc + P_XS);
        load_wT(WsTa, W1, tid);
        load_wT(WsTb, W1 + 128 * 128, tid);
        __syncthreads();
        // Phase A: batch-0 tiles by ALL CTAs
        proj_ranged(node_emb, b1, WsTa, WsTb, Xs,
                    blockIdx.x, T0, gridDim.x, T0, T1, T2, tid, wid, gq, tq);
        // Phase B: remaining tiles by nproj CTAs
        if ((int)blockIdx.x < nproj)
            proj_ranged(node_emb, b1, WsTa, WsTb, Xs,
                        T0 + blockIdx.x, ntiles_p, nproj, T0, T1, T2, tid, wid, gq, tq);
    }
    __syncthreads();   // proj smem use done before edge layout reuse

    // ================= EDGE phase (ticket-based) =================
    half*  QB0  = reinterpret_cast<half*>(smc + E_QB);
    half*  PB0  = reinterpret_cast<half*>(smc + E_PB);
    half*  HB   = reinterpret_cast<half*>(smc + E_HB);
    float* sels = reinterpret_cast<float*>(smc + E_SEL);
    int2*  idxs = reinterpret_cast<int2*>(smc + E_IDX);
    float* w1cs = reinterpret_cast<float*>(smc + E_W1C);
    const uint32_t qb_base = smem_u32(smc) + E_QB;
    const uint32_t pb_base = smem_u32(smc) + E_PB;

    const int oc_warp = (wid & 3) * 32;
    const int e_warp  = (wid >> 2) * 32;
    const int rsub  = lane >> 4;
    const int chunk = lane & 15;

    uint32_t w2a[8][2][4];
#pragma unroll
    for (int ks = 0; ks < 8; ++ks)
#pragma unroll
        for (int mt = 0; mt < 2; ++mt) {
            const int oc = oc_warp + mt * 16 + gq;
            const int k0 = ks * 16 + 2 * tq;
            w2a[ks][mt][0] = pack2(W2[k0 * 128 + oc],       W2[(k0 + 1) * 128 + oc]);
            w2a[ks][mt][1] = pack2(W2[k0 * 128 + oc + 8],   W2[(k0 + 1) * 128 + oc + 8]);
            w2a[ks][mt][2] = pack2(W2[(k0 + 8) * 128 + oc], W2[(k0 + 9) * 128 + oc]);
            w2a[ks][mt][3] = pack2(W2[(k0 + 8) * 128 + oc + 8], W2[(k0 + 9) * 128 + oc + 8]);
        }
    float b2v[2][2];
#pragma unroll
    for (int mt = 0; mt < 2; ++mt) {
        b2v[mt][0] = b2[oc_warp + mt * 16 + gq];
        b2v[mt][1] = b2[oc_warp + mt * 16 + gq + 8];
    }

    auto ebase = [&](int t) -> long long {
        const int b = t / bpb;
        return (long long)b * E + (long long)(t - b * bpb) * 64;
    };

    // prologue: grab two tickets
    if (tid == 0) {
        s_tk[0] = atomicAdd(&g_ticket, 1u);
        s_tk[1] = atomicAdd(&g_ticket, 1u);
    }
    __syncthreads();
    int t_cur = (s_tk[0] < (unsigned)ntiles_e) ? (int)s_tk[0] : -1;
    int t_nxt = (s_tk[1] < (unsigned)ntiles_e) ? (int)s_tk[1] : -1;

    if (t_cur >= 0) {
        if (tid == 0) wait_ready(t_cur / bpb, S0, S1, S2, S3);
        if (tid < 128) w1cs[tid] = W1[256 * 128 + tid];
        if (tid < 64) {
            const long long eb0 = ebase(t_cur);
            idxs[tid] = reinterpret_cast<const int2*>(edge_index)[eb0 + tid];
            sels[tid] = edge_sel[eb0 + tid];
        }
        __syncthreads();   // ready + idxs[0] + w1cs visible

        {
            const size_t rb = (size_t)(t_cur / bpb) * n_nodes;
#pragma unroll
            for (int r = 0; r < 4; ++r) {
                const int row = wid * 8 + 2 * r + rsub;
                int iv = idxs[row].y, iu = idxs[row].x;
                iv = min(max(iv, 0), n_nodes - 1);
                iu = min(max(iu, 0), n_nodes - 1);
                cp16(qb_base + (uint32_t)(row * 256 + chunk * 16),
                     Q_buf + (rb + iv) * 128 + chunk * 8);
                cp16(pb_base + (uint32_t)(row * 256 + chunk * 16),
                     P_buf + (rb + iu) * 128 + chunk * 8);
            }
            CP_COMMIT();
        }

        int i = 0;
        for (;;) {
            const int cur = i & 1, nxt = cur ^ 1;

            if (tid == 0 && t_nxt >= 0) wait_ready(t_nxt / bpb, S0, S1, S2, S3);
            if (tid < 64 && t_nxt >= 0) {
                const long long eb1 = ebase(t_nxt);
                idxs[nxt * 64 + tid] = reinterpret_cast<const int2*>(edge_index)[eb1 + tid];
                sels[nxt * 64 + tid] = edge_sel[eb1 + tid];
            }
            if (tid == 0)
                s_tk[0] = (t_nxt >= 0) ? atomicAdd(&g_ticket, 1u) : 0xFFFFFFFFu;
            __syncthreads();   // s1: idxs[nxt], s_tk, ready; HB WAR

            if (t_nxt >= 0) {
                const size_t rb1 = (size_t)(t_nxt / bpb) * n_nodes;
#pragma unroll
                for (int r = 0; r < 4; ++r) {
                    const int row = wid * 8 + 2 * r + rsub;
                    int iv = idxs[nxt * 64 + row].y, iu = idxs[nxt * 64 + row].x;
                    iv = min(max(iv, 0), n_nodes - 1);
                    iu = min(max(iu, 0), n_nodes - 1);
                    cp16(qb_base + (uint32_t)(nxt * 16384 + row * 256 + chunk * 16),
                         Q_buf + (rb1 + iv) * 128 + chunk * 8);
                    cp16(pb_base + (uint32_t)(nxt * 16384 + row * 256 + chunk * 16),
                         P_buf + (rb1 + iu) * 128 + chunk * 8);
                }
            }
            CP_COMMIT();       // always commit (possibly empty group)
            CP_WAIT1();        // stage cur arrived

            const unsigned nn = s_tk[0];   // read before s2 (tid0 rewrites only after next s1)

            // combine(t_cur)
            {
                const half* QBc = QB0 + cur * 8192;
                const half* PBc = PB0 + cur * 8192;
                const float4 wa = reinterpret_cast<const float4*>(w1cs + chunk * 8)[0];
                const float4 wb = reinterpret_cast<const float4*>(w1cs + chunk * 8)[1];
#pragma unroll
                for (int r = 0; r < 4; ++r) {
                    const int row = wid * 8 + 2 * r + rsub;
                    const uint4 q = *reinterpret_cast<const uint4*>(QBc + row * 128 + chunk * 8);
                    const uint4 p = *reinterpret_cast<const uint4*>(PBc + row * 128 + chunk * 8);
                    const float s = sels[cur * 64 + row];
                    const float2 p0 = unpack2(p.x), p1 = unpack2(p.y), p2 = unpack2(p.z), p3 = unpack2(p.w);
                    const float2 q0 = unpack2(q.x), q1 = unpack2(q.y), q2 = unpack2(q.z), q3 = unpack2(q.w);
                    uint4 h;
                    h.x = pack2(fmaxf(p0.x + q0.x + s * wa.x, 0.f),
                                fmaxf(p0.y + q0.y + s * wa.y, 0.f));
                    h.y = pack2(fmaxf(p1.x + q1.x + s * wa.z, 0.f),
                                fmaxf(p1.y + q1.y + s * wa.w, 0.f));
                    h.z = pack2(fmaxf(p2.x + q2.x + s * wb.x, 0.f),
                                fmaxf(p2.y + q2.y + s * wb.y, 0.f));
                    h.w = pack2(fmaxf(p3.x + q3.x + s * wb.z, 0.f),
                                fmaxf(p3.y + q3.y + s * wb.w, 0.f));
                    *reinterpret_cast<uint4*>(HB + row * LDH + chunk * 8) = h;
                }
            }
            __syncthreads();   // s2: HB visible

            // GEMM2 transposed (A = w2a regs, B = HB)
            float acc[2][4][4];
#pragma unroll
            for (int mt = 0; mt < 2; ++mt)
#pragma unroll
                for (int nt = 0; nt < 4; ++nt)
#pragma unroll
                    for (int k = 0; k < 4; ++k) acc[mt][nt][k] = 0.f;

#pragma unroll
            for (int ks = 0; ks < 8; ++ks) {
                const int k0 = ks * 16;
#pragma unroll
                for (int nt = 0; nt < 4; ++nt) {
                    const int e = e_warp + nt * 8 + gq;
                    const uint32_t b0 = lds32(HB + e * LDH + k0 + 2 * tq);
                    const uint32_t b1r = lds32(HB + e * LDH + k0 + 8 + 2 * tq);
                    mma16(acc[0][nt], w2a[ks][0], b0, b1r);
                    mma16(acc[1][nt], w2a[ks][1], b0, b1r);
                }
            }

            // epilogue
            {
                const long long eb = ebase(t_cur);
#pragma unroll
                for (int nt = 0; nt < 4; ++nt) {
                    const long long e0 = eb + e_warp + nt * 8 + 2 * tq;
#pragma unroll
                    for (int mt = 0; mt < 2; ++mt) {
                        const int oc = oc_warp + mt * 16 + gq;
                        __stcs(out + (size_t)e0 * 128 + oc,
                               fmaxf(acc[mt][nt][0] + b2v[mt][0], 0.f));
                        __stcs(out + (size_t)(e0 + 1) * 128 + oc,
                               fmaxf(acc[mt][nt][1] + b2v[mt][0], 0.f));
                        __stcs(out + (size_t)e0 * 128 + oc + 8,
                               fmaxf(acc[mt][nt][2] + b2v[mt][1], 0.f));
                        __stcs(out + (size_t)(e0 + 1) * 128 + oc + 8,
                               fmaxf(acc[mt][nt][3] + b2v[mt][1], 0.f));
                    }
                }
            }

            if (t_nxt < 0) break;
            t_cur = t_nxt;
            t_nxt = (nn < (unsigned)ntiles_e) ? (int)nn : -1;
            ++i;
        }
    }
    CP_WAIT0();
}

extern "C" void kernel_launch(void* const* d_in, const int* in_sizes, int n_in,
                              void* d_out, int out_size) {
    const float* node_emb   = (const float*)d_in[0];
    const int*   edge_index = (const int*)d_in[1];   // int32
    const float* edge_sel   = (const float*)d_in[2];
    const float* W1         = (const float*)d_in[3];
    const float* b1         = (const float*)d_in[4];
    const float* W2         = (const float*)d_in[5];
    const float* b2         = (const float*)d_in[6];
    float*       out        = (float*)d_out;

    const int B  = 4;
    const int E  = in_sizes[2] / B;
    const int n_nodes = in_sizes[0] / (B * 128);
    const int BN = B * n_nodes;

    const int ntiles_p = BN / 64;          // 6250 (exact)
    const int bpb      = E / 64;
    const int ntiles_e = B * bpb;

    int dev = 0, sms = 148;
    cudaGetDevice(&dev);
    cudaDeviceGetAttribute(&sms, cudaDevAttrMultiProcessorCount, dev);
    const int grid = 2 * sms;
    const int nproj = (grid * 3) / 8;

    cudaFuncSetAttribute(fused_kernel,
                         cudaFuncAttributeMaxDynamicSharedMemorySize, SMB);

    init_sync_kernel<<<1, 32>>>();
    fused_kernel<<<grid, 256, SMB>>>(node_emb, edge_index, edge_sel,
                                     W1, b1, W2, b2, out,
                                     E, bpb, n_nodes, ntiles_e, ntiles_p, nproj);
}